// round 9
// baseline (speedup 1.0000x reference)
#include <cuda_runtime.h>
#include <cuda_bf16.h>
#include <stdint.h>
#include <math.h>

#define G_    8
#define S_    16
#define H_    512
#define BM    64          // rows per CTA
#define NT    512         // threads per CTA (16 warps, 2x8 grid)
#define CH    32768       // one B chunk: [512 n][32 k] bf16

// ---------------- device weight scratch (static, allowed) ----------------
__device__ __nv_bfloat16 g_W2hi[G_*H_*H_];
__device__ __nv_bfloat16 g_W2lo[G_*H_*H_];
__device__ __nv_bfloat16 g_W3hi[G_*H_*H_];
__device__ __nv_bfloat16 g_W3lo[G_*H_*H_];

// ---------------- smem layout (bytes) ----------------
// AHI [64][256] u32 pairs : 0       .. 65536
// ALO                     : 65536   .. 131072
// B 3 x 32KB              : 131072  .. 229376  (xs overlays buf2; W4t+stg overlay in layer4)
#define SM_ALO  65536
#define SM_B    131072
#define SMEM_BYTES 229376

// ---------------- helpers ----------------
__device__ __forceinline__ float swishf(float v, float sp) {
    return v * __fdividef(1.0f, 1.0f + __expf(-v * sp)) * (1.0f / 1.1f);
}
__device__ __forceinline__ float softplusf(float b) { return log1pf(__expf(b)); }

__device__ __forceinline__ uint32_t bf16pair(float lo_elem, float hi_elem) {
    uint32_t r;
    asm("cvt.rn.bf16x2.f32 %0, %1, %2;" : "=r"(r) : "f"(hi_elem), "f"(lo_elem));
    return r;
}

// swizzled u32-pair index helpers (conflict-free for m16n8k16 frag access)
__device__ __forceinline__ int a_idx(int r, int p) { return r * 256 + (p ^ ((r & 7) << 2)); }
__device__ __forceinline__ int b_idx(int n, int p) { return n * 16  + (p ^ (((n >> 1) & 3) << 2)); }

__device__ __forceinline__ void mma16816(float* c,
    uint32_t a0, uint32_t a1, uint32_t a2, uint32_t a3, uint32_t b0, uint32_t b1) {
    asm volatile(
        "mma.sync.aligned.m16n8k16.row.col.f32.bf16.bf16.f32 "
        "{%0,%1,%2,%3},{%4,%5,%6,%7},{%8,%9},{%0,%1,%2,%3};"
        : "+f"(c[0]), "+f"(c[1]), "+f"(c[2]), "+f"(c[3])
        : "r"(a0), "r"(a1), "r"(a2), "r"(a3), "r"(b0), "r"(b1));
}

template<int N> __device__ __forceinline__ void cp_wait() {
    asm volatile("cp.async.wait_group %0;" :: "n"(N) : "memory");
}

// load one B chunk [512 n][32 k] bf16 (32KB) via cp.async, swizzled
__device__ __forceinline__ void load_chunk(uint32_t dst_base, const __nv_bfloat16* Wsrc,
                                           int kc, int tid) {
    #pragma unroll
    for (int l = 0; l < 4; ++l) {
        int j = tid + NT * l;           // 0..2047 16B chunks
        int n = j >> 2, q = j & 3;
        const void* src = Wsrc + (size_t)n * H_ + kc * 32 + q * 8;
        uint32_t dst = dst_base + n * 64 + ((q ^ ((n >> 1) & 3)) << 4);
        asm volatile("cp.async.cg.shared.global [%0], [%1], 16;" :: "r"(dst), "l"(src));
    }
    asm volatile("cp.async.commit_group;" ::: "memory");
}

// mma over one 32-wide k-chunk.  BOTH: Ah and Al passes (Bhi chunk); else Ah only.
template<bool BOTH>
__device__ __forceinline__ void mma_chunk(float (&acc)[2][8][4],
    const uint32_t* Ah, const uint32_t* Al, const uint32_t* Bp,
    int kc, int wm, int wn, int gq, int t) {
    #pragma unroll
    for (int kk = 0; kk < 2; ++kk) {
        uint32_t B0[8], B1[8];
        #pragma unroll
        for (int ni = 0; ni < 8; ++ni) {
            int n = wn * 64 + ni * 8 + gq;
            B0[ni] = Bp[b_idx(n, kk * 8 + t)];
            B1[ni] = Bp[b_idx(n, kk * 8 + 4 + t)];
        }
        int pb = kc * 16 + kk * 8;
        #pragma unroll
        for (int mi = 0; mi < 2; ++mi) {
            int r = wm * 32 + mi * 16;
            uint32_t a0 = Ah[a_idx(r + gq,     pb + t)];
            uint32_t a1 = Ah[a_idx(r + 8 + gq, pb + t)];
            uint32_t a2 = Ah[a_idx(r + gq,     pb + 4 + t)];
            uint32_t a3 = Ah[a_idx(r + 8 + gq, pb + 4 + t)];
            #pragma unroll
            for (int ni = 0; ni < 8; ++ni) mma16816(acc[mi][ni], a0, a1, a2, a3, B0[ni], B1[ni]);
        }
        if (BOTH) {
            #pragma unroll
            for (int mi = 0; mi < 2; ++mi) {
                int r = wm * 32 + mi * 16;
                uint32_t a0 = Al[a_idx(r + gq,     pb + t)];
                uint32_t a1 = Al[a_idx(r + 8 + gq, pb + t)];
                uint32_t a2 = Al[a_idx(r + gq,     pb + 4 + t)];
                uint32_t a3 = Al[a_idx(r + 8 + gq, pb + 4 + t)];
                #pragma unroll
                for (int ni = 0; ni < 8; ++ni) mma16816(acc[mi][ni], a0, a1, a2, a3, B0[ni], B1[ni]);
            }
        }
    }
}

// 32-chunk GEMM mainloop; 3-stage cp.async pipeline, one barrier per chunk.
// Entry: chunks 0,1 already committed into bufs 0,1.
__device__ __forceinline__ void run_gemm(float (&acc)[2][8][4],
    const uint32_t* Ah, const uint32_t* Al, const char* Bb, uint32_t smB,
    const __nv_bfloat16* Wh, const __nv_bfloat16* Wl,
    int wm, int wn, int gq, int t, int tid) {
    #pragma unroll
    for (int mi = 0; mi < 2; ++mi)
        #pragma unroll
        for (int ni = 0; ni < 8; ++ni)
            #pragma unroll
            for (int q = 0; q < 4; ++q) acc[mi][ni][q] = 0.0f;

    #pragma unroll 1
    for (int i = 0; i < 32; ++i) {
        if (i < 31) cp_wait<1>(); else cp_wait<0>();
        __syncthreads();                 // chunk i visible; buf (i+2)%3 free
        if (i < 30) {
            int c = i + 2;
            load_chunk(smB + (c % 3) * CH, (c & 1) ? Wl : Wh, c >> 1, tid);
        }
        const uint32_t* Bp = (const uint32_t*)(Bb + (i % 3) * CH);
        if (!(i & 1)) mma_chunk<true >(acc, Ah, Al, Bp, i >> 1, wm, wn, gq, t);
        else          mma_chunk<false>(acc, Ah, Al, Bp, i >> 1, wm, wn, gq, t);
    }
}

// ---------------- prep: split W2/W3 into bf16 hi/lo ----------------
__global__ void prep_kernel(const float* __restrict__ W2, const float* __restrict__ W3) {
    const int n = G_ * H_ * H_;
    for (int i = blockIdx.x * blockDim.x + threadIdx.x; i < n; i += gridDim.x * blockDim.x) {
        float w = W2[i];
        __nv_bfloat16 h = __float2bfloat16(w);
        g_W2hi[i] = h;
        g_W2lo[i] = __float2bfloat16(w - __bfloat162float(h));
        w = W3[i];
        h = __float2bfloat16(w);
        g_W3hi[i] = h;
        g_W3lo[i] = __float2bfloat16(w - __bfloat162float(h));
    }
}

// ---------------- fused kernel ----------------
__global__ void __launch_bounds__(NT, 1) fused_kernel(
    const float* __restrict__ x,
    const float* __restrict__ W1, const float* __restrict__ b1, const float* __restrict__ beta1,
    const float* __restrict__ b2, const float* __restrict__ beta2,
    const float* __restrict__ b3, const float* __restrict__ beta3,
    const float* __restrict__ W4, const float* __restrict__ b4,
    float* __restrict__ out)
{
    extern __shared__ char sm[];
    uint32_t* Ah = (uint32_t*)sm;
    uint32_t* Al = (uint32_t*)(sm + SM_ALO);
    char*     Bb = sm + SM_B;
    float*    xs = (float*)(sm + SM_B + 2 * CH);   // overlays buf2 (dead until chunk 2)
    const uint32_t smB = (uint32_t)__cvta_generic_to_shared(Bb);

    const int tid = threadIdx.x, wid = tid >> 5, lane = tid & 31;
    const int g  = blockIdx.y;
    const int b0 = blockIdx.x * BM;
    const int wm = wid >> 3, wn = wid & 7;        // warp grid 2x8
    const int gq = lane >> 2, t = lane & 3;

    const __nv_bfloat16* W2h = g_W2hi + (size_t)g * H_ * H_;
    const __nv_bfloat16* W2l = g_W2lo + (size_t)g * H_ * H_;
    const __nv_bfloat16* W3h = g_W3hi + (size_t)g * H_ * H_;
    const __nv_bfloat16* W3l = g_W3lo + (size_t)g * H_ * H_;

    // ---- stage x tile [64x16] (stride 20) into buf2 overlay ----
    for (int i = tid; i < BM * S_; i += NT) {
        int r = i >> 4, s = i & 15;
        xs[r * 20 + s] = x[(size_t)(b0 + r) * (G_ * S_) + g * S_ + s];
    }
    __syncthreads();

    // ---- prefetch layer-2 chunks 0,1 (bufs 0,1; xs in buf2 untouched) ----
    load_chunk(smB,      W2h, 0, tid);
    load_chunk(smB + CH, W2l, 0, tid);

    // ================= layer 1 (fp32 SIMT) -> Ah/Al =================
    {
        const float sp1 = softplusf(beta1[g]);
        const int t2 = tid & 255, rh = tid >> 8;     // t2 -> col pair, rh -> row half
        const int c0 = t2 * 2;
        const float* w0 = W1 + ((size_t)g * H_ + c0) * S_;
        float wreg[32];
        #pragma unroll
        for (int q = 0; q < 8; ++q) {
            float4 v = *(const float4*)(w0 + q * 4);
            wreg[q * 4 + 0] = v.x; wreg[q * 4 + 1] = v.y;
            wreg[q * 4 + 2] = v.z; wreg[q * 4 + 3] = v.w;
        }
        const float bb0 = b1[(size_t)g * H_ + c0];
        const float bb1 = b1[(size_t)g * H_ + c0 + 1];
        for (int r = rh * 32; r < rh * 32 + 32; ++r) {
            const float* xr = xs + r * 20;
            float v0 = bb0, v1 = bb1;
            #pragma unroll
            for (int q = 0; q < 4; ++q) {
                float4 xv = *(const float4*)(xr + q * 4);
                v0 = fmaf(xv.x, wreg[q*4+0], v0); v1 = fmaf(xv.x, wreg[16+q*4+0], v1);
                v0 = fmaf(xv.y, wreg[q*4+1], v0); v1 = fmaf(xv.y, wreg[16+q*4+1], v1);
                v0 = fmaf(xv.z, wreg[q*4+2], v0); v1 = fmaf(xv.z, wreg[16+q*4+2], v1);
                v0 = fmaf(xv.w, wreg[q*4+3], v0); v1 = fmaf(xv.w, wreg[16+q*4+3], v1);
            }
            v0 = swishf(v0, sp1);
            v1 = swishf(v1, sp1);
            uint32_t hp = bf16pair(v0, v1);
            float h0 = __uint_as_float(hp << 16);
            float h1 = __uint_as_float(hp & 0xffff0000u);
            uint32_t lp = bf16pair(v0 - h0, v1 - h1);
            int ai = a_idx(r, t2);
            Ah[ai] = hp;
            Al[ai] = lp;
        }
    }
    __syncthreads();

    float acc[2][8][4];

    // ================= layer 2 (bf16 3-pass HMMA) =================
    run_gemm(acc, Ah, Al, Bb, smB, W2h, W2l, wm, wn, gq, t, tid);
    __syncthreads();                                  // all A reads done

    // prefetch layer-3 chunks 0,1 (bufs 0,1 free) — overlaps epilogue
    load_chunk(smB,      W3h, 0, tid);
    load_chunk(smB + CH, W3l, 0, tid);

    // layer-2 epilogue: bias + swish -> hi/lo split -> rewrite Ah/Al
    {
        const float sp2 = softplusf(beta2[g]);
        const float* bg = b2 + (size_t)g * H_;
        #pragma unroll
        for (int ni = 0; ni < 8; ++ni) {
            int cb = wn * 64 + ni * 8 + 2 * t;
            float be = __ldg(bg + cb), bo = __ldg(bg + cb + 1);
            int p = wn * 32 + ni * 4 + t;
            #pragma unroll
            for (int mi = 0; mi < 2; ++mi) {
                int r0 = wm * 32 + mi * 16 + gq;
                float v00 = swishf(acc[mi][ni][0] + be, sp2);
                float v01 = swishf(acc[mi][ni][1] + bo, sp2);
                float v10 = swishf(acc[mi][ni][2] + be, sp2);
                float v11 = swishf(acc[mi][ni][3] + bo, sp2);
                uint32_t hp0 = bf16pair(v00, v01);
                float h0 = __uint_as_float(hp0 << 16);
                float h1 = __uint_as_float(hp0 & 0xffff0000u);
                uint32_t lp0 = bf16pair(v00 - h0, v01 - h1);
                int ai0 = a_idx(r0, p);
                Ah[ai0] = hp0; Al[ai0] = lp0;
                uint32_t hp1 = bf16pair(v10, v11);
                float h2 = __uint_as_float(hp1 << 16);
                float h3 = __uint_as_float(hp1 & 0xffff0000u);
                uint32_t lp1 = bf16pair(v10 - h2, v11 - h3);
                int ai1 = a_idx(r0 + 8, p);
                Ah[ai1] = hp1; Al[ai1] = lp1;
            }
        }
    }
    __syncthreads();

    // ================= layer 3 (bf16 3-pass HMMA) =================
    run_gemm(acc, Ah, Al, Bb, smB, W3h, W3l, wm, wn, gq, t, tid);
    __syncthreads();                                  // B bufs free for W4t overlay

    // layer-3 epilogue: bias + swish in registers
    {
        const float sp3 = softplusf(beta3[g]);
        const float* bg = b3 + (size_t)g * H_;
        #pragma unroll
        for (int ni = 0; ni < 8; ++ni) {
            int cb = wn * 64 + ni * 8 + 2 * t;
            float be = __ldg(bg + cb), bo = __ldg(bg + cb + 1);
            #pragma unroll
            for (int mi = 0; mi < 2; ++mi) {
                acc[mi][ni][0] = swishf(acc[mi][ni][0] + be, sp3);
                acc[mi][ni][1] = swishf(acc[mi][ni][1] + bo, sp3);
                acc[mi][ni][2] = swishf(acc[mi][ni][2] + be, sp3);
                acc[mi][ni][3] = swishf(acc[mi][ni][3] + bo, sp3);
            }
        }
    }

    // ================= layer 4 (fp32 SIMT from registers) =================
    {
        float* W4t = (float*)Bb;                        // [512][20] f32, 40KB
        const float* W4g = W4 + (size_t)g * S_ * H_;
        #pragma unroll
        for (int l = 0; l < 16; ++l) {
            int i = tid + NT * l;                        // 8192 elements
            int c = i & 511, s = i >> 9;
            W4t[c * 20 + s] = W4g[(size_t)s * H_ + c];
        }
        __syncthreads();

        float pacc[2][2][16];    // [mi][row-half][s]
        #pragma unroll
        for (int a = 0; a < 2; ++a)
            #pragma unroll
            for (int bq = 0; bq < 2; ++bq)
                #pragma unroll
                for (int s = 0; s < 16; ++s) pacc[a][bq][s] = 0.0f;

        #pragma unroll
        for (int ni = 0; ni < 8; ++ni) {
            int ce = wn * 64 + ni * 8 + 2 * t;
            float we[16], wo[16];
            #pragma unroll
            for (int q = 0; q < 4; ++q) {
                float4 v = *(const float4*)(W4t + ce * 20 + q * 4);
                we[q*4+0] = v.x; we[q*4+1] = v.y; we[q*4+2] = v.z; we[q*4+3] = v.w;
                float4 u = *(const float4*)(W4t + (ce + 1) * 20 + q * 4);
                wo[q*4+0] = u.x; wo[q*4+1] = u.y; wo[q*4+2] = u.z; wo[q*4+3] = u.w;
            }
            #pragma unroll
            for (int mi = 0; mi < 2; ++mi) {
                float h00 = acc[mi][ni][0], h01 = acc[mi][ni][1];
                float h10 = acc[mi][ni][2], h11 = acc[mi][ni][3];
                #pragma unroll
                for (int s = 0; s < 16; ++s) {
                    pacc[mi][0][s] = fmaf(h00, we[s], fmaf(h01, wo[s], pacc[mi][0][s]));
                    pacc[mi][1][s] = fmaf(h10, we[s], fmaf(h11, wo[s], pacc[mi][1][s]));
                }
            }
        }
        // reduce over the 4 t-lanes
        #pragma unroll
        for (int mi = 0; mi < 2; ++mi)
            #pragma unroll
            for (int bq = 0; bq < 2; ++bq)
                #pragma unroll
                for (int s = 0; s < 16; ++s) {
                    float v = pacc[mi][bq][s];
                    v += __shfl_xor_sync(0xffffffffu, v, 1);
                    v += __shfl_xor_sync(0xffffffffu, v, 2);
                    pacc[mi][bq][s] = v;
                }
        // stage per-wn partials: [8][64][16] f32 (32KB) after W4t (40KB)
        float* stg = (float*)(Bb + 40960);
        if (t == 0) {
            #pragma unroll
            for (int mi = 0; mi < 2; ++mi)
                #pragma unroll
                for (int bq = 0; bq < 2; ++bq) {
                    int r = wm * 32 + mi * 16 + bq * 8 + gq;
                    #pragma unroll
                    for (int s = 0; s < 16; ++s)
                        stg[(wn * 64 + r) * 16 + s] = pacc[mi][bq][s];
                }
        }
        __syncthreads();
        // final: sum 8 wn-partials + b4, write out (2 outputs per thread)
        {
            int r = tid >> 3, s0 = (tid & 7) * 2;
            float o0 = b4[(size_t)g * S_ + s0];
            float o1 = b4[(size_t)g * S_ + s0 + 1];
            #pragma unroll
            for (int w = 0; w < 8; ++w) {
                float2 v = *(const float2*)(stg + (w * 64 + r) * 16 + s0);
                o0 += v.x; o1 += v.y;
            }
            *(float2*)&out[(size_t)(b0 + r) * (G_ * S_) + g * S_ + s0] = make_float2(o0, o1);
        }
    }
}

// ================= launch =================
extern "C" void kernel_launch(void* const* d_in, const int* in_sizes, int n_in,
                              void* d_out, int out_size) {
    const float* x     = (const float*)d_in[0];
    const float* W1    = (const float*)d_in[1];
    const float* b1    = (const float*)d_in[2];
    const float* beta1 = (const float*)d_in[3];
    const float* W2    = (const float*)d_in[4];
    const float* b2    = (const float*)d_in[5];
    const float* beta2 = (const float*)d_in[6];
    const float* W3    = (const float*)d_in[7];
    const float* b3    = (const float*)d_in[8];
    const float* beta3 = (const float*)d_in[9];
    const float* W4    = (const float*)d_in[10];
    const float* b4    = (const float*)d_in[11];
    float* out = (float*)d_out;

    int Brows = in_sizes[0] / (G_ * S_);

    cudaFuncSetAttribute(fused_kernel, cudaFuncAttributeMaxDynamicSharedMemorySize, SMEM_BYTES);

    prep_kernel<<<512, 256>>>(W2, W3);

    dim3 grid(Brows / BM, G_);
    fused_kernel<<<grid, NT, SMEM_BYTES>>>(x, W1, b1, beta1, b2, beta2, b3, beta3, W4, b4, out);
}

// round 13
// speedup vs baseline: 2.0466x; 2.0466x over previous
#include <cuda_runtime.h>
#include <cuda_fp16.h>
#include <stdint.h>
#include <math.h>

#define G_    8
#define S_    16
#define H_    512
#define BM    64          // rows per CTA
#define NT    512         // threads per CTA (16 warps, 2x8 grid)
#define CH    32768       // one B chunk: [512 n][32 k] fp16

// ---------------- device weight scratch (static, allowed) ----------------
__device__ __half g_W2f[G_*H_*H_];
__device__ __half g_W3f[G_*H_*H_];

// ---------------- smem layout (bytes) ----------------
// A  [64][256] u32 (fp16 pairs) : 0      .. 65536
// B  3 x 32KB                   : 65536  .. 163840  (xs overlays buf2; W4t+stg overlay in layer4)
#define SM_B    65536
#define SMEM_BYTES 163840

// ---------------- helpers ----------------
__device__ __forceinline__ float swishf(float v, float sp) {
    return v * __fdividef(1.0f, 1.0f + __expf(-v * sp)) * (1.0f / 1.1f);
}
__device__ __forceinline__ float softplusf(float b) { return log1pf(__expf(b)); }

// pack two floats -> fp16x2 (lo_elem in low 16 bits)
__device__ __forceinline__ uint32_t f16pair(float lo_elem, float hi_elem) {
    uint32_t r;
    asm("cvt.rn.f16x2.f32 %0, %1, %2;" : "=r"(r) : "f"(hi_elem), "f"(lo_elem));
    return r;
}

// swizzled u32-pair index helpers (conflict-free for m16n8k16 frag access)
__device__ __forceinline__ int a_idx(int r, int p) { return r * 256 + (p ^ ((r & 7) << 2)); }
__device__ __forceinline__ int b_idx(int n, int p) { return n * 16  + (p ^ (((n >> 1) & 3) << 2)); }

__device__ __forceinline__ void mma16816(float* c,
    uint32_t a0, uint32_t a1, uint32_t a2, uint32_t a3, uint32_t b0, uint32_t b1) {
    asm volatile(
        "mma.sync.aligned.m16n8k16.row.col.f32.f16.f16.f32 "
        "{%0,%1,%2,%3},{%4,%5,%6,%7},{%8,%9},{%0,%1,%2,%3};"
        : "+f"(c[0]), "+f"(c[1]), "+f"(c[2]), "+f"(c[3])
        : "r"(a0), "r"(a1), "r"(a2), "r"(a3), "r"(b0), "r"(b1));
}

template<int N> __device__ __forceinline__ void cp_wait() {
    asm volatile("cp.async.wait_group %0;" :: "n"(N) : "memory");
}

// load one B chunk [512 n][32 k] fp16 (32KB) via cp.async, swizzled
__device__ __forceinline__ void load_chunk(uint32_t dst_base, const __half* Wsrc,
                                           int kc, int tid) {
    #pragma unroll
    for (int l = 0; l < 4; ++l) {
        int j = tid + NT * l;           // 0..2047 16B chunks
        int n = j >> 2, q = j & 3;
        const void* src = Wsrc + (size_t)n * H_ + kc * 32 + q * 8;
        uint32_t dst = dst_base + n * 64 + ((q ^ ((n >> 1) & 3)) << 4);
        asm volatile("cp.async.cg.shared.global [%0], [%1], 16;" :: "r"(dst), "l"(src));
    }
    asm volatile("cp.async.commit_group;" ::: "memory");
}

// mma over one 32-wide k-chunk (single fp16 pass)
__device__ __forceinline__ void mma_chunk(float (&acc)[2][8][4],
    const uint32_t* A, const uint32_t* Bp,
    int kc, int wm, int wn, int gq, int t) {
    #pragma unroll
    for (int kk = 0; kk < 2; ++kk) {
        uint32_t B0[8], B1[8];
        #pragma unroll
        for (int ni = 0; ni < 8; ++ni) {
            int n = wn * 64 + ni * 8 + gq;
            B0[ni] = Bp[b_idx(n, kk * 8 + t)];
            B1[ni] = Bp[b_idx(n, kk * 8 + 4 + t)];
        }
        int pb = kc * 16 + kk * 8;
        #pragma unroll
        for (int mi = 0; mi < 2; ++mi) {
            int r = wm * 32 + mi * 16;
            uint32_t a0 = A[a_idx(r + gq,     pb + t)];
            uint32_t a1 = A[a_idx(r + 8 + gq, pb + t)];
            uint32_t a2 = A[a_idx(r + gq,     pb + 4 + t)];
            uint32_t a3 = A[a_idx(r + 8 + gq, pb + 4 + t)];
            #pragma unroll
            for (int ni = 0; ni < 8; ++ni) mma16816(acc[mi][ni], a0, a1, a2, a3, B0[ni], B1[ni]);
        }
    }
}

// 16-chunk GEMM mainloop; 3-stage cp.async pipeline, one barrier per chunk.
// Entry: chunks 0,1 already committed into bufs 0,1.
__device__ __forceinline__ void run_gemm(float (&acc)[2][8][4],
    const uint32_t* A, const char* Bb, uint32_t smB, const __half* W,
    int wm, int wn, int gq, int t, int tid) {
    #pragma unroll
    for (int mi = 0; mi < 2; ++mi)
        #pragma unroll
        for (int ni = 0; ni < 8; ++ni)
            #pragma unroll
            for (int q = 0; q < 4; ++q) acc[mi][ni][q] = 0.0f;

    #pragma unroll 1
    for (int i = 0; i < 16; ++i) {
        if (i < 15) cp_wait<1>(); else cp_wait<0>();
        __syncthreads();                 // chunk i visible; buf (i+2)%3 free
        if (i < 14) {
            int c = i + 2;
            load_chunk(smB + (c % 3) * CH, W, c, tid);
        }
        const uint32_t* Bp = (const uint32_t*)(Bb + (i % 3) * CH);
        mma_chunk(acc, A, Bp, i, wm, wn, gq, t);
    }
}

// ---------------- prep: convert W2/W3 to fp16 ----------------
__global__ void prep_kernel(const float* __restrict__ W2, const float* __restrict__ W3) {
    const int n = G_ * H_ * H_;
    for (int i = blockIdx.x * blockDim.x + threadIdx.x; i < n; i += gridDim.x * blockDim.x) {
        g_W2f[i] = __float2half_rn(W2[i]);
        g_W3f[i] = __float2half_rn(W3[i]);
    }
}

// ---------------- fused kernel ----------------
__global__ void __launch_bounds__(NT, 1) fused_kernel(
    const float* __restrict__ x,
    const float* __restrict__ W1, const float* __restrict__ b1, const float* __restrict__ beta1,
    const float* __restrict__ b2, const float* __restrict__ beta2,
    const float* __restrict__ b3, const float* __restrict__ beta3,
    const float* __restrict__ W4, const float* __restrict__ b4,
    float* __restrict__ out)
{
    extern __shared__ char sm[];
    uint32_t* A  = (uint32_t*)sm;
    char*     Bb = sm + SM_B;
    float*    xs = (float*)(sm + SM_B + 2 * CH);   // overlays buf2 (dead until chunk 2)
    const uint32_t smB = (uint32_t)__cvta_generic_to_shared(Bb);

    const int tid = threadIdx.x, wid = tid >> 5, lane = tid & 31;
    const int g  = blockIdx.y;
    const int b0 = blockIdx.x * BM;
    const int wm = wid >> 3, wn = wid & 7;        // warp grid 2x8
    const int gq = lane >> 2, t = lane & 3;

    const __half* W2f = g_W2f + (size_t)g * H_ * H_;
    const __half* W3f = g_W3f + (size_t)g * H_ * H_;

    // ---- stage x tile [64x16] (stride 20) into buf2 overlay ----
    for (int i = tid; i < BM * S_; i += NT) {
        int r = i >> 4, s = i & 15;
        xs[r * 20 + s] = x[(size_t)(b0 + r) * (G_ * S_) + g * S_ + s];
    }
    __syncthreads();

    // ---- prefetch layer-2 chunks 0,1 (bufs 0,1; xs in buf2 untouched) ----
    load_chunk(smB,      W2f, 0, tid);
    load_chunk(smB + CH, W2f, 1, tid);

    // ================= layer 1 (fp32 SIMT) -> A (fp16) =================
    {
        const float sp1 = softplusf(beta1[g]);
        const int t2 = tid & 255, rh = tid >> 8;     // t2 -> col pair, rh -> row half
        const int c0 = t2 * 2;
        const float* w0 = W1 + ((size_t)g * H_ + c0) * S_;
        float wreg[32];
        #pragma unroll
        for (int q = 0; q < 8; ++q) {
            float4 v = *(const float4*)(w0 + q * 4);
            wreg[q * 4 + 0] = v.x; wreg[q * 4 + 1] = v.y;
            wreg[q * 4 + 2] = v.z; wreg[q * 4 + 3] = v.w;
        }
        const float bb0 = b1[(size_t)g * H_ + c0];
        const float bb1 = b1[(size_t)g * H_ + c0 + 1];
        for (int r = rh * 32; r < rh * 32 + 32; ++r) {
            const float* xr = xs + r * 20;
            float v0 = bb0, v1 = bb1;
            #pragma unroll
            for (int q = 0; q < 4; ++q) {
                float4 xv = *(const float4*)(xr + q * 4);
                v0 = fmaf(xv.x, wreg[q*4+0], v0); v1 = fmaf(xv.x, wreg[16+q*4+0], v1);
                v0 = fmaf(xv.y, wreg[q*4+1], v0); v1 = fmaf(xv.y, wreg[16+q*4+1], v1);
                v0 = fmaf(xv.z, wreg[q*4+2], v0); v1 = fmaf(xv.z, wreg[16+q*4+2], v1);
                v0 = fmaf(xv.w, wreg[q*4+3], v0); v1 = fmaf(xv.w, wreg[16+q*4+3], v1);
            }
            v0 = swishf(v0, sp1);
            v1 = swishf(v1, sp1);
            A[a_idx(r, t2)] = f16pair(v0, v1);
        }
    }
    __syncthreads();

    float acc[2][8][4];

    // ================= layer 2 (fp16 single-pass HMMA) =================
    run_gemm(acc, A, Bb, smB, W2f, wm, wn, gq, t, tid);
    __syncthreads();                                  // all A reads done

    // prefetch layer-3 chunks 0,1 (bufs 0,1 free) — overlaps epilogue
    load_chunk(smB,      W3f, 0, tid);
    load_chunk(smB + CH, W3f, 1, tid);

    // layer-2 epilogue: bias + swish -> fp16 -> rewrite A
    {
        const float sp2 = softplusf(beta2[g]);
        const float* bg = b2 + (size_t)g * H_;
        #pragma unroll
        for (int ni = 0; ni < 8; ++ni) {
            int cb = wn * 64 + ni * 8 + 2 * t;
            float be = __ldg(bg + cb), bo = __ldg(bg + cb + 1);
            int p = wn * 32 + ni * 4 + t;
            #pragma unroll
            for (int mi = 0; mi < 2; ++mi) {
                int r0 = wm * 32 + mi * 16 + gq;
                float v00 = swishf(acc[mi][ni][0] + be, sp2);
                float v01 = swishf(acc[mi][ni][1] + bo, sp2);
                float v10 = swishf(acc[mi][ni][2] + be, sp2);
                float v11 = swishf(acc[mi][ni][3] + bo, sp2);
                A[a_idx(r0, p)]     = f16pair(v00, v01);
                A[a_idx(r0 + 8, p)] = f16pair(v10, v11);
            }
        }
    }
    __syncthreads();

    // ================= layer 3 (fp16 single-pass HMMA) =================
    run_gemm(acc, A, Bb, smB, W3f, wm, wn, gq, t, tid);
    __syncthreads();                                  // B bufs free for W4t overlay

    // layer-3 epilogue: bias + swish in registers
    {
        const float sp3 = softplusf(beta3[g]);
        const float* bg = b3 + (size_t)g * H_;
        #pragma unroll
        for (int ni = 0; ni < 8; ++ni) {
            int cb = wn * 64 + ni * 8 + 2 * t;
            float be = __ldg(bg + cb), bo = __ldg(bg + cb + 1);
            #pragma unroll
            for (int mi = 0; mi < 2; ++mi) {
                acc[mi][ni][0] = swishf(acc[mi][ni][0] + be, sp3);
                acc[mi][ni][1] = swishf(acc[mi][ni][1] + bo, sp3);
                acc[mi][ni][2] = swishf(acc[mi][ni][2] + be, sp3);
                acc[mi][ni][3] = swishf(acc[mi][ni][3] + bo, sp3);
            }
        }
    }

    // ================= layer 4 (fp32 SIMT from registers) =================
    {
        float* W4t = (float*)Bb;                        // [512][20] f32, 40KB
        const float* W4g = W4 + (size_t)g * S_ * H_;
        #pragma unroll
        for (int l = 0; l < 16; ++l) {
            int i = tid + NT * l;                        // 8192 elements
            int c = i & 511, s = i >> 9;
            W4t[c * 20 + s] = W4g[(size_t)s * H_ + c];
        }
        __syncthreads();

        float pacc[2][2][16];    // [mi][row-half][s]
        #pragma unroll
        for (int a = 0; a < 2; ++a)
            #pragma unroll
            for (int bq = 0; bq < 2; ++bq)
                #pragma unroll
                for (int s = 0; s < 16; ++s) pacc[a][bq][s] = 0.0f;

        #pragma unroll
        for (int ni = 0; ni < 8; ++ni) {
            int ce = wn * 64 + ni * 8 + 2 * t;
            float we[16], wo[16];
            #pragma unroll
            for (int q = 0; q < 4; ++q) {
                float4 v = *(const float4*)(W4t + ce * 20 + q * 4);
                we[q*4+0] = v.x; we[q*4+1] = v.y; we[q*4+2] = v.z; we[q*4+3] = v.w;
                float4 u = *(const float4*)(W4t + (ce + 1) * 20 + q * 4);
                wo[q*4+0] = u.x; wo[q*4+1] = u.y; wo[q*4+2] = u.z; wo[q*4+3] = u.w;
            }
            #pragma unroll
            for (int mi = 0; mi < 2; ++mi) {
                float h00 = acc[mi][ni][0], h01 = acc[mi][ni][1];
                float h10 = acc[mi][ni][2], h11 = acc[mi][ni][3];
                #pragma unroll
                for (int s = 0; s < 16; ++s) {
                    pacc[mi][0][s] = fmaf(h00, we[s], fmaf(h01, wo[s], pacc[mi][0][s]));
                    pacc[mi][1][s] = fmaf(h10, we[s], fmaf(h11, wo[s], pacc[mi][1][s]));
                }
            }
        }
        // reduce over the 4 t-lanes
        #pragma unroll
        for (int mi = 0; mi < 2; ++mi)
            #pragma unroll
            for (int bq = 0; bq < 2; ++bq)
                #pragma unroll
                for (int s = 0; s < 16; ++s) {
                    float v = pacc[mi][bq][s];
                    v += __shfl_xor_sync(0xffffffffu, v, 1);
                    v += __shfl_xor_sync(0xffffffffu, v, 2);
                    pacc[mi][bq][s] = v;
                }
        // stage per-wn partials: [8][64][16] f32 (32KB) after W4t (40KB)
        float* stg = (float*)(Bb + 40960);
        if (t == 0) {
            #pragma unroll
            for (int mi = 0; mi < 2; ++mi)
                #pragma unroll
                for (int bq = 0; bq < 2; ++bq) {
                    int r = wm * 32 + mi * 16 + bq * 8 + gq;
                    #pragma unroll
                    for (int s = 0; s < 16; ++s)
                        stg[(wn * 64 + r) * 16 + s] = pacc[mi][bq][s];
                }
        }
        __syncthreads();
        // final: sum 8 wn-partials + b4, write out (2 outputs per thread)
        {
            int r = tid >> 3, s0 = (tid & 7) * 2;
            float o0 = b4[(size_t)g * S_ + s0];
            float o1 = b4[(size_t)g * S_ + s0 + 1];
            #pragma unroll
            for (int w = 0; w < 8; ++w) {
                float2 v = *(const float2*)(stg + (w * 64 + r) * 16 + s0);
                o0 += v.x; o1 += v.y;
            }
            *(float2*)&out[(size_t)(b0 + r) * (G_ * S_) + g * S_ + s0] = make_float2(o0, o1);
        }
    }
}

// ================= launch =================
extern "C" void kernel_launch(void* const* d_in, const int* in_sizes, int n_in,
                              void* d_out, int out_size) {
    const float* x     = (const float*)d_in[0];
    const float* W1    = (const float*)d_in[1];
    const float* b1    = (const float*)d_in[2];
    const float* beta1 = (const float*)d_in[3];
    const float* W2    = (const float*)d_in[4];
    const float* b2    = (const float*)d_in[5];
    const float* beta2 = (const float*)d_in[6];
    const float* W3    = (const float*)d_in[7];
    const float* b3    = (const float*)d_in[8];
    const float* beta3 = (const float*)d_in[9];
    const float* W4    = (const float*)d_in[10];
    const float* b4    = (const float*)d_in[11];
    float* out = (float*)d_out;

    int Brows = in_sizes[0] / (G_ * S_);

    cudaFuncSetAttribute(fused_kernel, cudaFuncAttributeMaxDynamicSharedMemorySize, SMEM_BYTES);

    prep_kernel<<<512, 256>>>(W2, W3);

    dim3 grid(Brows / BM, G_);
    fused_kernel<<<grid, NT, SMEM_BYTES>>>(x, W1, b1, beta1, b2, beta2, b3, beta3, W4, b4, out);
}

// round 14
// speedup vs baseline: 2.6081x; 1.2744x over previous
#include <cuda_runtime.h>
#include <cuda_fp16.h>
#include <stdint.h>
#include <math.h>

#define G_    8
#define S_    16
#define H_    512
#define BM    64          // rows per CTA
#define NT    512         // threads per CTA (16 warps, 2x8 grid)
#define CH    65536       // one B chunk: [512 n][64 k] fp16 = 64KB

// ---------------- device weight scratch (static, allowed) ----------------
__device__ __half g_W2f[G_*H_*H_];
__device__ __half g_W3f[G_*H_*H_];

// ---------------- smem layout (bytes) ----------------
// A  [64][256] u32 (fp16 pairs) : 0      .. 65536   (1KB per row)
// B  2 x 64KB                   : 65536  .. 196608  (xs overlays buf1; W4t+stg overlay in layer4)
#define SM_B    65536
#define SMEM_BYTES 196608

// ---------------- helpers ----------------
__device__ __forceinline__ float swishf(float v, float sp) {
    return v * __fdividef(1.0f, 1.0f + __expf(-v * sp)) * (1.0f / 1.1f);
}
__device__ __forceinline__ float softplusf(float b) { return log1pf(__expf(b)); }

__device__ __forceinline__ uint32_t f16pair(float lo_elem, float hi_elem) {
    uint32_t r;
    asm("cvt.rn.f16x2.f32 %0, %1, %2;" : "=r"(r) : "f"(hi_elem), "f"(lo_elem));
    return r;
}

// A tile swizzled pair index (row = 256 pairs = 1KB)
__device__ __forceinline__ int a_idx(int r, int p) { return r * 256 + (p ^ ((r & 7) << 2)); }

__device__ __forceinline__ void mma16816(float* c,
    uint32_t a0, uint32_t a1, uint32_t a2, uint32_t a3, uint32_t b0, uint32_t b1) {
    asm volatile(
        "mma.sync.aligned.m16n8k16.row.col.f32.f16.f16.f32 "
        "{%0,%1,%2,%3},{%4,%5,%6,%7},{%8,%9},{%0,%1,%2,%3};"
        : "+f"(c[0]), "+f"(c[1]), "+f"(c[2]), "+f"(c[3])
        : "r"(a0), "r"(a1), "r"(a2), "r"(a3), "r"(b0), "r"(b1));
}

__device__ __forceinline__ void ldsm4(uint32_t& r0, uint32_t& r1, uint32_t& r2, uint32_t& r3,
                                      uint32_t addr) {
    asm volatile("ldmatrix.sync.aligned.m8n8.x4.shared.b16 {%0,%1,%2,%3}, [%4];"
                 : "=r"(r0), "=r"(r1), "=r"(r2), "=r"(r3) : "r"(addr));
}

template<int N> __device__ __forceinline__ void cp_wait() {
    asm volatile("cp.async.wait_group %0;" :: "n"(N) : "memory");
}

// load one B chunk [512 n][64 k] fp16 (64KB) via cp.async, swizzled rows of 128B
__device__ __forceinline__ void load_chunk(uint32_t dst_base, const __half* Wsrc,
                                           int kc, int tid) {
    #pragma unroll
    for (int l = 0; l < 8; ++l) {
        int j = tid + NT * l;           // 0..4095 16B chunks
        int n = j >> 3, q = j & 7;
        const void* src = Wsrc + (size_t)n * H_ + kc * 64 + q * 8;
        uint32_t dst = dst_base + n * 128 + ((q ^ (n & 7)) << 4);
        asm volatile("cp.async.cg.shared.global [%0], [%1], 16;" :: "r"(dst), "l"(src));
    }
    asm volatile("cp.async.commit_group;" ::: "memory");
}

// 8-chunk (64k each) GEMM mainloop; 2-stage pipeline, one barrier per chunk.
// Entry: chunk 0 committed into buf0; nothing else in flight.
__device__ __forceinline__ void run_gemm(float (&acc)[2][8][4],
    uint32_t smA, uint32_t smB, const __half* W, int tid) {
    const int lane = tid & 31, wid = tid >> 5;
    const int wm = wid >> 3, wn = wid & 7;
    const int l7 = lane & 7;
    const uint32_t xsw = (uint32_t)(l7 << 2);        // swizzle XOR, pair units
    const int mhalf = (lane >> 3) & 1;               // A: row half; B: k half
    const int kg = lane >> 4;                        // A: k group;  B: j select
    const uint32_t mhalf4 = mhalf * 4, kg4 = kg * 4;

    // per-lane bases
    uint32_t aBase[2];
    #pragma unroll
    for (int mi = 0; mi < 2; ++mi)
        aBase[mi] = smA + (uint32_t)(wm * 32 + mi * 16 + mhalf * 8 + l7) * 1024;
    uint32_t nOff[4];
    #pragma unroll
    for (int jj = 0; jj < 4; ++jj)
        nOff[jj] = (uint32_t)(wn * 64 + (2 * jj + kg) * 8 + l7) * 128;

    #pragma unroll
    for (int mi = 0; mi < 2; ++mi)
        #pragma unroll
        for (int ni = 0; ni < 8; ++ni)
            #pragma unroll
            for (int q = 0; q < 4; ++q) acc[mi][ni][q] = 0.0f;

    #pragma unroll 1
    for (int i = 0; i < 8; ++i) {
        cp_wait<0>();                    // chunk i resident
        __syncthreads();                 // + all reads of chunk i-1 complete
        if (i < 7) load_chunk(smB + ((i + 1) & 1) * CH, W, i + 1, tid);
        const uint32_t bufB = smB + (i & 1) * CH;

        #pragma unroll
        for (int kk = 0; kk < 4; ++kk) {
            uint32_t B0[8], B1[8];
            uint32_t boff = (((uint32_t)(kk * 8) + mhalf4) ^ xsw) * 4;
            #pragma unroll
            for (int jj = 0; jj < 4; ++jj)
                ldsm4(B0[2*jj], B1[2*jj], B0[2*jj+1], B1[2*jj+1], bufB + nOff[jj] + boff);
            uint32_t aoff = (((uint32_t)(i * 32 + kk * 8) + kg4) ^ xsw) * 4;
            #pragma unroll
            for (int mi = 0; mi < 2; ++mi) {
                uint32_t a0, a1, a2, a3;
                ldsm4(a0, a1, a2, a3, aBase[mi] + aoff);
                #pragma unroll
                for (int ni = 0; ni < 8; ++ni)
                    mma16816(acc[mi][ni], a0, a1, a2, a3, B0[ni], B1[ni]);
            }
        }
    }
}

// ---------------- prep: convert W2/W3 to fp16 ----------------
__global__ void prep_kernel(const float* __restrict__ W2, const float* __restrict__ W3) {
    const int n = G_ * H_ * H_;
    for (int i = blockIdx.x * blockDim.x + threadIdx.x; i < n; i += gridDim.x * blockDim.x) {
        g_W2f[i] = __float2half_rn(W2[i]);
        g_W3f[i] = __float2half_rn(W3[i]);
    }
}

// ---------------- fused kernel ----------------
__global__ void __launch_bounds__(NT, 1) fused_kernel(
    const float* __restrict__ x,
    const float* __restrict__ W1, const float* __restrict__ b1, const float* __restrict__ beta1,
    const float* __restrict__ b2, const float* __restrict__ beta2,
    const float* __restrict__ b3, const float* __restrict__ beta3,
    const float* __restrict__ W4, const float* __restrict__ b4,
    float* __restrict__ out)
{
    extern __shared__ char sm[];
    uint32_t* A  = (uint32_t*)sm;
    char*     Bb = sm + SM_B;
    float*    xs = (float*)(sm + SM_B + CH);       // overlays buf1 (dead until chunk-1 load)
    const uint32_t smA = (uint32_t)__cvta_generic_to_shared(sm);
    const uint32_t smB = (uint32_t)__cvta_generic_to_shared(Bb);

    const int tid = threadIdx.x, wid = tid >> 5, lane = tid & 31;
    const int g  = blockIdx.y;
    const int b0 = blockIdx.x * BM;
    const int wm = wid >> 3, wn = wid & 7;        // warp grid 2x8
    const int gq = lane >> 2, t = lane & 3;

    const __half* W2f = g_W2f + (size_t)g * H_ * H_;
    const __half* W3f = g_W3f + (size_t)g * H_ * H_;

    // ---- stage x tile [64x16] (stride 20) into buf1 overlay ----
    for (int i = tid; i < BM * S_; i += NT) {
        int r = i >> 4, s = i & 15;
        xs[r * 20 + s] = x[(size_t)(b0 + r) * (G_ * S_) + g * S_ + s];
    }
    __syncthreads();

    // ---- prefetch layer-2 chunk 0 (buf0; xs in buf1 untouched) ----
    load_chunk(smB, W2f, 0, tid);

    // ================= layer 1 (fp32 SIMT) -> A (fp16) =================
    {
        const float sp1 = softplusf(beta1[g]);
        const int t2 = tid & 255, rh = tid >> 8;     // t2 -> col pair, rh -> row half
        const int c0 = t2 * 2;
        const float* w0 = W1 + ((size_t)g * H_ + c0) * S_;
        float wreg[32];
        #pragma unroll
        for (int q = 0; q < 8; ++q) {
            float4 v = *(const float4*)(w0 + q * 4);
            wreg[q * 4 + 0] = v.x; wreg[q * 4 + 1] = v.y;
            wreg[q * 4 + 2] = v.z; wreg[q * 4 + 3] = v.w;
        }
        const float bb0 = b1[(size_t)g * H_ + c0];
        const float bb1 = b1[(size_t)g * H_ + c0 + 1];
        for (int r = rh * 32; r < rh * 32 + 32; ++r) {
            const float* xr = xs + r * 20;
            float v0 = bb0, v1 = bb1;
            #pragma unroll
            for (int q = 0; q < 4; ++q) {
                float4 xv = *(const float4*)(xr + q * 4);
                v0 = fmaf(xv.x, wreg[q*4+0], v0); v1 = fmaf(xv.x, wreg[16+q*4+0], v1);
                v0 = fmaf(xv.y, wreg[q*4+1], v0); v1 = fmaf(xv.y, wreg[16+q*4+1], v1);
                v0 = fmaf(xv.z, wreg[q*4+2], v0); v1 = fmaf(xv.z, wreg[16+q*4+2], v1);
                v0 = fmaf(xv.w, wreg[q*4+3], v0); v1 = fmaf(xv.w, wreg[16+q*4+3], v1);
            }
            v0 = swishf(v0, sp1);
            v1 = swishf(v1, sp1);
            A[a_idx(r, t2)] = f16pair(v0, v1);
        }
    }
    __syncthreads();

    float acc[2][8][4];

    // ================= layer 2 (fp16 HMMA, ldmatrix) =================
    run_gemm(acc, smA, smB, W2f, tid);
    __syncthreads();                                  // all A + chunk-7 reads done

    // prefetch layer-3 chunk 0 (buf0 free) — overlaps epilogue
    load_chunk(smB, W3f, 0, tid);

    // layer-2 epilogue: bias + swish -> fp16 -> rewrite A
    {
        const float sp2 = softplusf(beta2[g]);
        const float* bg = b2 + (size_t)g * H_;
        #pragma unroll
        for (int ni = 0; ni < 8; ++ni) {
            int cb = wn * 64 + ni * 8 + 2 * t;
            float be = __ldg(bg + cb), bo = __ldg(bg + cb + 1);
            int p = wn * 32 + ni * 4 + t;
            #pragma unroll
            for (int mi = 0; mi < 2; ++mi) {
                int r0 = wm * 32 + mi * 16 + gq;
                float v00 = swishf(acc[mi][ni][0] + be, sp2);
                float v01 = swishf(acc[mi][ni][1] + bo, sp2);
                float v10 = swishf(acc[mi][ni][2] + be, sp2);
                float v11 = swishf(acc[mi][ni][3] + bo, sp2);
                A[a_idx(r0, p)]     = f16pair(v00, v01);
                A[a_idx(r0 + 8, p)] = f16pair(v10, v11);
            }
        }
    }
    __syncthreads();

    // ================= layer 3 (fp16 HMMA, ldmatrix) =================
    run_gemm(acc, smA, smB, W3f, tid);
    __syncthreads();                                  // B bufs free for W4t overlay

    // layer-3 epilogue: bias + swish in registers
    {
        const float sp3 = softplusf(beta3[g]);
        const float* bg = b3 + (size_t)g * H_;
        #pragma unroll
        for (int ni = 0; ni < 8; ++ni) {
            int cb = wn * 64 + ni * 8 + 2 * t;
            float be = __ldg(bg + cb), bo = __ldg(bg + cb + 1);
            #pragma unroll
            for (int mi = 0; mi < 2; ++mi) {
                acc[mi][ni][0] = swishf(acc[mi][ni][0] + be, sp3);
                acc[mi][ni][1] = swishf(acc[mi][ni][1] + bo, sp3);
                acc[mi][ni][2] = swishf(acc[mi][ni][2] + be, sp3);
                acc[mi][ni][3] = swishf(acc[mi][ni][3] + bo, sp3);
            }
        }
    }

    // ================= layer 4 (fp32 SIMT from registers) =================
    {
        float* W4t = (float*)Bb;                        // [512][20] f32, 40KB
        const float* W4g = W4 + (size_t)g * S_ * H_;
        #pragma unroll
        for (int l = 0; l < 16; ++l) {
            int i = tid + NT * l;                        // 8192 elements
            int c = i & 511, s = i >> 9;
            W4t[c * 20 + s] = W4g[(size_t)s * H_ + c];
        }
        __syncthreads();

        float pacc[2][2][16];    // [mi][row-half][s]
        #pragma unroll
        for (int a = 0; a < 2; ++a)
            #pragma unroll
            for (int bq = 0; bq < 2; ++bq)
                #pragma unroll
                for (int s = 0; s < 16; ++s) pacc[a][bq][s] = 0.0f;

        #pragma unroll
        for (int ni = 0; ni < 8; ++ni) {
            int ce = wn * 64 + ni * 8 + 2 * t;
            float we[16], wo[16];
            #pragma unroll
            for (int q = 0; q < 4; ++q) {
                float4 v = *(const float4*)(W4t + ce * 20 + q * 4);
                we[q*4+0] = v.x; we[q*4+1] = v.y; we[q*4+2] = v.z; we[q*4+3] = v.w;
                float4 u = *(const float4*)(W4t + (ce + 1) * 20 + q * 4);
                wo[q*4+0] = u.x; wo[q*4+1] = u.y; wo[q*4+2] = u.z; wo[q*4+3] = u.w;
            }
            #pragma unroll
            for (int mi = 0; mi < 2; ++mi) {
                float h00 = acc[mi][ni][0], h01 = acc[mi][ni][1];
                float h10 = acc[mi][ni][2], h11 = acc[mi][ni][3];
                #pragma unroll
                for (int s = 0; s < 16; ++s) {
                    pacc[mi][0][s] = fmaf(h00, we[s], fmaf(h01, wo[s], pacc[mi][0][s]));
                    pacc[mi][1][s] = fmaf(h10, we[s], fmaf(h11, wo[s], pacc[mi][1][s]));
                }
            }
        }
        // reduce over the 4 t-lanes
        #pragma unroll
        for (int mi = 0; mi < 2; ++mi)
            #pragma unroll
            for (int bq = 0; bq < 2; ++bq)
                #pragma unroll
                for (int s = 0; s < 16; ++s) {
                    float v = pacc[mi][bq][s];
                    v += __shfl_xor_sync(0xffffffffu, v, 1);
                    v += __shfl_xor_sync(0xffffffffu, v, 2);
                    pacc[mi][bq][s] = v;
                }
        // stage per-wn partials: [8][64][16] f32 (32KB) after W4t (40KB)
        float* stg = (float*)(Bb + 40960);
        if (t == 0) {
            #pragma unroll
            for (int mi = 0; mi < 2; ++mi)
                #pragma unroll
                for (int bq = 0; bq < 2; ++bq) {
                    int r = wm * 32 + mi * 16 + bq * 8 + gq;
                    #pragma unroll
                    for (int s = 0; s < 16; ++s)
                        stg[(wn * 64 + r) * 16 + s] = pacc[mi][bq][s];
                }
        }
        __syncthreads();
        // final: sum 8 wn-partials + b4, write out (2 outputs per thread)
        {
            int r = tid >> 3, s0 = (tid & 7) * 2;
            float o0 = b4[(size_t)g * S_ + s0];
            float o1 = b4[(size_t)g * S_ + s0 + 1];
            #pragma unroll
            for (int w = 0; w < 8; ++w) {
                float2 v = *(const float2*)(stg + (w * 64 + r) * 16 + s0);
                o0 += v.x; o1 += v.y;
            }
            *(float2*)&out[(size_t)(b0 + r) * (G_ * S_) + g * S_ + s0] = make_float2(o0, o1);
        }
    }
}

// ================= launch =================
extern "C" void kernel_launch(void* const* d_in, const int* in_sizes, int n_in,
                              void* d_out, int out_size) {
    const float* x     = (const float*)d_in[0];
    const float* W1    = (const float*)d_in[1];
    const float* b1    = (const float*)d_in[2];
    const float* beta1 = (const float*)d_in[3];
    const float* W2    = (const float*)d_in[4];
    const float* b2    = (const float*)d_in[5];
    const float* beta2 = (const float*)d_in[6];
    const float* W3    = (const float*)d_in[7];
    const float* b3    = (const float*)d_in[8];
    const float* beta3 = (const float*)d_in[9];
    const float* W4    = (const float*)d_in[10];
    const float* b4    = (const float*)d_in[11];
    float* out = (float*)d_out;

    int Brows = in_sizes[0] / (G_ * S_);

    cudaFuncSetAttribute(fused_kernel, cudaFuncAttributeMaxDynamicSharedMemorySize, SMEM_BYTES);

    prep_kernel<<<512, 256>>>(W2, W3);

    dim3 grid(Brows / BM, G_);
    fused_kernel<<<grid, NT, SMEM_BYTES>>>(x, W1, b1, beta1, b2, beta2, b3, beta3, W4, b4, out);
}

// round 16
// speedup vs baseline: 2.8793x; 1.1040x over previous
#include <cuda_runtime.h>
#include <cuda_fp16.h>
#include <stdint.h>
#include <math.h>

#define G_    8
#define S_    16
#define H_    512
#define BM    64          // rows per CTA
#define NT    512         // threads per CTA (16 warps, 2x8 grid)
#define CH    65536       // one B chunk: [512 n][64 k] fp16 = 64KB

// ---------------- device weight scratch (static, allowed) ----------------
__device__ __half g_W2f[G_*H_*H_];
__device__ __half g_W3f[G_*H_*H_];
__device__ __half g_W4f[G_*S_*H_];

// ---------------- smem layout (bytes) ----------------
// A  [64][256] u32 (fp16 pairs) : 0      .. 65536   (1KB per row)
// B  2 x 64KB                   : 65536  .. 196608  (xs overlays buf1; W4 tile + stg overlay buf0)
#define SM_B    65536
#define SMEM_BYTES 196608

// ---------------- helpers ----------------
__device__ __forceinline__ float swishf(float v, float sp) {
    return v * __fdividef(1.0f, 1.0f + __expf(-v * sp)) * (1.0f / 1.1f);
}
__device__ __forceinline__ float softplusf(float b) { return log1pf(__expf(b)); }

__device__ __forceinline__ uint32_t f16pair(float lo_elem, float hi_elem) {
    uint32_t r;
    asm("cvt.rn.f16x2.f32 %0, %1, %2;" : "=r"(r) : "f"(hi_elem), "f"(lo_elem));
    return r;
}

// A/W4 tile swizzled pair index (row = 256 pairs = 1KB)
__device__ __forceinline__ int a_idx(int r, int p) { return r * 256 + (p ^ ((r & 7) << 2)); }

__device__ __forceinline__ void mma16816(float* c,
    uint32_t a0, uint32_t a1, uint32_t a2, uint32_t a3, uint32_t b0, uint32_t b1) {
    asm volatile(
        "mma.sync.aligned.m16n8k16.row.col.f32.f16.f16.f32 "
        "{%0,%1,%2,%3},{%4,%5,%6,%7},{%8,%9},{%0,%1,%2,%3};"
        : "+f"(c[0]), "+f"(c[1]), "+f"(c[2]), "+f"(c[3])
        : "r"(a0), "r"(a1), "r"(a2), "r"(a3), "r"(b0), "r"(b1));
}

__device__ __forceinline__ void ldsm4(uint32_t& r0, uint32_t& r1, uint32_t& r2, uint32_t& r3,
                                      uint32_t addr) {
    asm volatile("ldmatrix.sync.aligned.m8n8.x4.shared.b16 {%0,%1,%2,%3}, [%4];"
                 : "=r"(r0), "=r"(r1), "=r"(r2), "=r"(r3) : "r"(addr));
}

template<int N> __device__ __forceinline__ void cp_wait() {
    asm volatile("cp.async.wait_group %0;" :: "n"(N) : "memory");
}

// load one B chunk [512 n][64 k] fp16 (64KB) via cp.async, swizzled rows of 128B
__device__ __forceinline__ void load_chunk(uint32_t dst_base, const __half* Wsrc,
                                           int kc, int tid) {
    #pragma unroll
    for (int l = 0; l < 8; ++l) {
        int j = tid + NT * l;           // 0..4095 16B chunks
        int n = j >> 3, q = j & 7;
        const void* src = Wsrc + (size_t)n * H_ + kc * 64 + q * 8;
        uint32_t dst = dst_base + n * 128 + ((q ^ (n & 7)) << 4);
        asm volatile("cp.async.cg.shared.global [%0], [%1], 16;" :: "r"(dst), "l"(src));
    }
    asm volatile("cp.async.commit_group;" ::: "memory");
}

// load W4 tile [16 n][512 k] fp16 (16KB), 1KB rows swizzled like A
__device__ __forceinline__ void load_w4(uint32_t dst_base, const __half* W4src, int tid) {
    #pragma unroll
    for (int l = 0; l < 2; ++l) {
        int j = tid + NT * l;           // 0..1023 16B chunks
        int n = j >> 6, q = j & 63;
        const void* src = W4src + (size_t)n * H_ + q * 8;
        uint32_t dst = dst_base + n * 1024 + ((q ^ (n & 7)) << 4);
        asm volatile("cp.async.cg.shared.global [%0], [%1], 16;" :: "r"(dst), "l"(src));
    }
    asm volatile("cp.async.commit_group;" ::: "memory");
}

// 8-chunk (64k each) GEMM mainloop; 2-stage pipeline, one barrier per chunk.
// Entry: chunk 0 committed into buf0.  At i==7, buf0 is free:
//   NEXT==1 -> prefetch next layer's chunk 0 there; NEXT==2 -> prefetch W4 tile.
template<int NEXT>
__device__ __forceinline__ void run_gemm(float (&acc)[2][8][4],
    uint32_t smA, uint32_t smB, const __half* W, const __half* Wn, int tid) {
    const int lane = tid & 31, wid = tid >> 5;
    const int wm = wid >> 3, wn = wid & 7;
    const int l7 = lane & 7;
    const uint32_t xsw = (uint32_t)(l7 << 2);        // swizzle XOR, pair units
    const int mhalf = (lane >> 3) & 1;               // A: row half; B: k half
    const int kg = lane >> 4;                        // A: k group;  B: j select
    const uint32_t mhalf4 = mhalf * 4, kg4 = kg * 4;

    uint32_t aBase[2];
    #pragma unroll
    for (int mi = 0; mi < 2; ++mi)
        aBase[mi] = smA + (uint32_t)(wm * 32 + mi * 16 + mhalf * 8 + l7) * 1024;
    uint32_t nOff[4];
    #pragma unroll
    for (int jj = 0; jj < 4; ++jj)
        nOff[jj] = (uint32_t)(wn * 64 + (2 * jj + kg) * 8 + l7) * 128;

    #pragma unroll
    for (int mi = 0; mi < 2; ++mi)
        #pragma unroll
        for (int ni = 0; ni < 8; ++ni)
            #pragma unroll
            for (int q = 0; q < 4; ++q) acc[mi][ni][q] = 0.0f;

    #pragma unroll 1
    for (int i = 0; i < 8; ++i) {
        cp_wait<0>();                    // chunk i resident
        __syncthreads();                 // + all reads of chunk i-1 complete
        if (i < 7)           load_chunk(smB + ((i + 1) & 1) * CH, W, i + 1, tid);
        else if (NEXT == 1)  load_chunk(smB, Wn, 0, tid);        // buf0 free
        else if (NEXT == 2)  load_w4(smB, Wn, tid);              // buf0 free
        const uint32_t bufB = smB + (i & 1) * CH;

        #pragma unroll
        for (int kk = 0; kk < 4; ++kk) {
            uint32_t B0[8], B1[8];
            uint32_t boff = (((uint32_t)(kk * 8) + mhalf4) ^ xsw) * 4;
            #pragma unroll
            for (int jj = 0; jj < 4; ++jj)
                ldsm4(B0[2*jj], B1[2*jj], B0[2*jj+1], B1[2*jj+1], bufB + nOff[jj] + boff);
            uint32_t aoff = (((uint32_t)(i * 32 + kk * 8) + kg4) ^ xsw) * 4;
            #pragma unroll
            for (int mi = 0; mi < 2; ++mi) {
                uint32_t a0, a1, a2, a3;
                ldsm4(a0, a1, a2, a3, aBase[mi] + aoff);
                #pragma unroll
                for (int ni = 0; ni < 8; ++ni)
                    mma16816(acc[mi][ni], a0, a1, a2, a3, B0[ni], B1[ni]);
            }
        }
    }
}

// ---------------- prep: convert W2/W3/W4 to fp16 ----------------
__global__ void prep_kernel(const float* __restrict__ W2, const float* __restrict__ W3,
                            const float* __restrict__ W4) {
    const int n = G_ * H_ * H_;
    for (int i = blockIdx.x * blockDim.x + threadIdx.x; i < n; i += gridDim.x * blockDim.x) {
        g_W2f[i] = __float2half_rn(W2[i]);
        g_W3f[i] = __float2half_rn(W3[i]);
    }
    const int m = G_ * S_ * H_;
    for (int i = blockIdx.x * blockDim.x + threadIdx.x; i < m; i += gridDim.x * blockDim.x)
        g_W4f[i] = __float2half_rn(W4[i]);
}

// ---------------- fused kernel ----------------
__global__ void __launch_bounds__(NT, 1) fused_kernel(
    const float* __restrict__ x,
    const float* __restrict__ W1, const float* __restrict__ b1, const float* __restrict__ beta1,
    const float* __restrict__ b2, const float* __restrict__ beta2,
    const float* __restrict__ b3, const float* __restrict__ beta3,
    const float* __restrict__ b4,
    float* __restrict__ out)
{
    extern __shared__ char sm[];
    uint32_t* A  = (uint32_t*)sm;
    char*     Bb = sm + SM_B;
    float*    xs = (float*)(sm + SM_B + CH);       // overlays buf1 (dead until chunk-1 load)
    const uint32_t smA = (uint32_t)__cvta_generic_to_shared(sm);
    const uint32_t smB = (uint32_t)__cvta_generic_to_shared(Bb);

    const int tid = threadIdx.x, wid = tid >> 5, lane = tid & 31;
    const int g  = blockIdx.y;
    const int b0 = blockIdx.x * BM;
    const int wm = wid >> 3, wn = wid & 7;        // warp grid 2x8
    const int gq = lane >> 2, t = lane & 3;

    const __half* W2f = g_W2f + (size_t)g * H_ * H_;
    const __half* W3f = g_W3f + (size_t)g * H_ * H_;
    const __half* W4f = g_W4f + (size_t)g * S_ * H_;

    // ---- stage x tile [64x16] (stride 20) into buf1 overlay ----
    for (int i = tid; i < BM * S_; i += NT) {
        int r = i >> 4, s = i & 15;
        xs[r * 20 + s] = x[(size_t)(b0 + r) * (G_ * S_) + g * S_ + s];
    }
    __syncthreads();

    // ---- prefetch layer-2 chunk 0 (buf0; xs in buf1 untouched) ----
    load_chunk(smB, W2f, 0, tid);

    // ================= layer 1 (fp32 SIMT) -> A (fp16) =================
    {
        const float sp1 = softplusf(beta1[g]);
        const int t2 = tid & 255, rh = tid >> 8;     // t2 -> col pair, rh -> row half
        const int c0 = t2 * 2;
        const float* w0 = W1 + ((size_t)g * H_ + c0) * S_;
        float wreg[32];
        #pragma unroll
        for (int q = 0; q < 8; ++q) {
            float4 v = *(const float4*)(w0 + q * 4);
            wreg[q * 4 + 0] = v.x; wreg[q * 4 + 1] = v.y;
            wreg[q * 4 + 2] = v.z; wreg[q * 4 + 3] = v.w;
        }
        const float bb0 = b1[(size_t)g * H_ + c0];
        const float bb1 = b1[(size_t)g * H_ + c0 + 1];
        for (int r = rh * 32; r < rh * 32 + 32; ++r) {
            const float* xr = xs + r * 20;
            float v0 = bb0, v1 = bb1;
            #pragma unroll
            for (int q = 0; q < 4; ++q) {
                float4 xv = *(const float4*)(xr + q * 4);
                v0 = fmaf(xv.x, wreg[q*4+0], v0); v1 = fmaf(xv.x, wreg[16+q*4+0], v1);
                v0 = fmaf(xv.y, wreg[q*4+1], v0); v1 = fmaf(xv.y, wreg[16+q*4+1], v1);
                v0 = fmaf(xv.z, wreg[q*4+2], v0); v1 = fmaf(xv.z, wreg[16+q*4+2], v1);
                v0 = fmaf(xv.w, wreg[q*4+3], v0); v1 = fmaf(xv.w, wreg[16+q*4+3], v1);
            }
            v0 = swishf(v0, sp1);
            v1 = swishf(v1, sp1);
            A[a_idx(r, t2)] = f16pair(v0, v1);
        }
    }
    __syncthreads();

    float acc[2][8][4];

    // ================= layer 2 (fp16 HMMA) — tail-prefetches W3 chunk 0 =================
    run_gemm<1>(acc, smA, smB, W2f, W3f, tid);
    __syncthreads();                                  // all A + chunk-7 reads done

    // layer-2 epilogue: bias + swish -> fp16 -> rewrite A
    {
        const float sp2 = softplusf(beta2[g]);
        const float* bg = b2 + (size_t)g * H_;
        #pragma unroll
        for (int ni = 0; ni < 8; ++ni) {
            int cb = wn * 64 + ni * 8 + 2 * t;
            float be = __ldg(bg + cb), bo = __ldg(bg + cb + 1);
            int p = wn * 32 + ni * 4 + t;
            #pragma unroll
            for (int mi = 0; mi < 2; ++mi) {
                int r0 = wm * 32 + mi * 16 + gq;
                float v00 = swishf(acc[mi][ni][0] + be, sp2);
                float v01 = swishf(acc[mi][ni][1] + bo, sp2);
                float v10 = swishf(acc[mi][ni][2] + be, sp2);
                float v11 = swishf(acc[mi][ni][3] + bo, sp2);
                A[a_idx(r0, p)]     = f16pair(v00, v01);
                A[a_idx(r0 + 8, p)] = f16pair(v10, v11);
            }
        }
    }
    __syncthreads();

    // ================= layer 3 (fp16 HMMA) — tail-prefetches W4 tile =================
    run_gemm<2>(acc, smA, smB, W3f, W4f, tid);
    __syncthreads();                                  // all A + chunk-7 reads done

    // layer-3 epilogue: bias + swish -> fp16 -> rewrite A (h3)
    {
        const float sp3 = softplusf(beta3[g]);
        const float* bg = b3 + (size_t)g * H_;
        #pragma unroll
        for (int ni = 0; ni < 8; ++ni) {
            int cb = wn * 64 + ni * 8 + 2 * t;
            float be = __ldg(bg + cb), bo = __ldg(bg + cb + 1);
            int p = wn * 32 + ni * 4 + t;
            #pragma unroll
            for (int mi = 0; mi < 2; ++mi) {
                int r0 = wm * 32 + mi * 16 + gq;
                float v00 = swishf(acc[mi][ni][0] + be, sp3);
                float v01 = swishf(acc[mi][ni][1] + bo, sp3);
                float v10 = swishf(acc[mi][ni][2] + be, sp3);
                float v11 = swishf(acc[mi][ni][3] + bo, sp3);
                A[a_idx(r0, p)]     = f16pair(v00, v01);
                A[a_idx(r0 + 8, p)] = f16pair(v10, v11);
            }
        }
    }
    cp_wait<0>();          // W4 tile resident (prefetched in layer-3 tail)
    __syncthreads();       // + h3 writes visible

    // ================= layer 4 (fp16 HMMA, k split over wn) =================
    {
        const int l7 = lane & 7;
        const uint32_t xsw = (uint32_t)(l7 << 2);
        const int khalf = (lane >> 3) & 1;
        const int ntile = lane >> 4;
        const uint32_t khalf4 = khalf * 4, kg4 = ntile * 4;   // A reuses same lane roles

        float a4[2][2][4];
        #pragma unroll
        for (int mi = 0; mi < 2; ++mi)
            #pragma unroll
            for (int ni = 0; ni < 2; ++ni)
                #pragma unroll
                for (int q = 0; q < 4; ++q) a4[mi][ni][q] = 0.0f;

        uint32_t aBase[2];
        #pragma unroll
        for (int mi = 0; mi < 2; ++mi)
            aBase[mi] = smA + (uint32_t)(wm * 32 + mi * 16 + khalf * 8 + l7) * 1024;
        const uint32_t bRow = smB + (uint32_t)(ntile * 8 + l7) * 1024;  // W4 row n

        #pragma unroll
        for (int kk = 0; kk < 4; ++kk) {
            uint32_t pb = (uint32_t)(wn * 32 + kk * 8);
            uint32_t B0[2], B1[2];
            ldsm4(B0[0], B1[0], B0[1], B1[1], bRow + ((pb + khalf4) ^ xsw) * 4);
            uint32_t aoff = ((pb + kg4) ^ xsw) * 4;
            #pragma unroll
            for (int mi = 0; mi < 2; ++mi) {
                uint32_t a0, a1, a2, a3;
                ldsm4(a0, a1, a2, a3, aBase[mi] + aoff);
                #pragma unroll
                for (int ni = 0; ni < 2; ++ni)
                    mma16816(a4[mi][ni], a0, a1, a2, a3, B0[ni], B1[ni]);
            }
        }

        // stage per-wn partials: [8 wn][64 rows][16 cols] f32 (32KB) after W4 tile (16KB)
        float* stg = (float*)(Bb + 16384);
        #pragma unroll
        for (int mi = 0; mi < 2; ++mi) {
            int r0 = wm * 32 + mi * 16 + gq;
            #pragma unroll
            for (int ni = 0; ni < 2; ++ni) {
                int c = ni * 8 + 2 * t;
                stg[(wn * 64 + r0) * 16 + c]         = a4[mi][ni][0];
                stg[(wn * 64 + r0) * 16 + c + 1]     = a4[mi][ni][1];
                stg[(wn * 64 + r0 + 8) * 16 + c]     = a4[mi][ni][2];
                stg[(wn * 64 + r0 + 8) * 16 + c + 1] = a4[mi][ni][3];
            }
        }
        __syncthreads();
        // final: sum 8 wn-partials + b4, write out (2 outputs per thread)
        {
            int r = tid >> 3, s0 = (tid & 7) * 2;
            float o0 = b4[(size_t)g * S_ + s0];
            float o1 = b4[(size_t)g * S_ + s0 + 1];
            #pragma unroll
            for (int w = 0; w < 8; ++w) {
                float2 v = *(const float2*)(stg + (w * 64 + r) * 16 + s0);
                o0 += v.x; o1 += v.y;
            }
            *(float2*)&out[(size_t)(b0 + r) * (G_ * S_) + g * S_ + s0] = make_float2(o0, o1);
        }
    }
}

// ================= launch =================
extern "C" void kernel_launch(void* const* d_in, const int* in_sizes, int n_in,
                              void* d_out, int out_size) {
    const float* x     = (const float*)d_in[0];
    const float* W1    = (const float*)d_in[1];
    const float* b1    = (const float*)d_in[2];
    const float* beta1 = (const float*)d_in[3];
    const float* W2    = (const float*)d_in[4];
    const float* b2    = (const float*)d_in[5];
    const float* beta2 = (const float*)d_in[6];
    const float* W3    = (const float*)d_in[7];
    const float* b3    = (const float*)d_in[8];
    const float* beta3 = (const float*)d_in[9];
    const float* W4    = (const float*)d_in[10];
    const float* b4    = (const float*)d_in[11];
    float* out = (float*)d_out;

    int Brows = in_sizes[0] / (G_ * S_);

    cudaFuncSetAttribute(fused_kernel, cudaFuncAttributeMaxDynamicSharedMemorySize, SMEM_BYTES);

    prep_kernel<<<512, 256>>>(W2, W3, W4);

    dim3 grid(Brows / BM, G_);
    fused_kernel<<<grid, NT, SMEM_BYTES>>>(x, W1, b1, beta1, b2, beta2, b3, beta3, b4, out);
}